// round 2
// baseline (speedup 1.0000x reference)
#include <cuda_runtime.h>
#include <cuda_bf16.h>

// Problem shape (LogRegBaseline): B=64, T=2048, V=512
#define BB     64
#define TT     2048
#define VV     512
#define TM1    (TT - 1)          // 2047 output positions
#define CHUNK  128               // time positions per varying-emit CTA
#define NCHUNK (TT / CHUNK)      // 16 (16*128 = 2048 covers all activation times)
#define FILLG  18                // fill row-groups per batch (~1 full wave)

// Scratch (device globals; no allocation allowed)
__device__ int   g_ft[BB * VV];                 // first-activation time per (b, v); TT if never
__device__ int   g_tlast[BB];                   // max activation time per batch (0 if none)
__device__ float g_Wt[VV * VV];                 // W transposed: Wt[v*VV + u] = W[u*VV + v]
__device__ float g_states[BB * NCHUNK * VV];    // prefix logits at each chunk boundary
__device__ float g_S[BB * VV];                  // steady-state row: bias + sum of all activated cols

// ---------------------------------------------------------------------------
// Kernel 1: first activation time per (b, v) + block-max t_last.
// Grid: BB blocks x VV threads. Coalesced t-scan, collective early exit.
// ---------------------------------------------------------------------------
__global__ void find_first(const float* __restrict__ codes) {
    const int b = blockIdx.x;
    const int v = threadIdx.x;
    __shared__ int s_rem;
    __shared__ int s_red[VV];
    if (v == 0) s_rem = VV;
    __syncthreads();

    const float* p = codes + (size_t)b * TT * VV + v;
    int  myft  = TT;
    bool found = false;

    for (int t0 = 0; t0 < TT; t0 += 8) {
        if (!found) {
            float x[8];
#pragma unroll
            for (int k = 0; k < 8; k++) x[k] = p[(size_t)(t0 + k) * VV];
#pragma unroll
            for (int k = 0; k < 8; k++) {
                if (!found && x[k] != 0.0f) { found = true; myft = t0 + k; }
            }
            if (found) atomicAdd(&s_rem, -1);
        }
        __syncthreads();
        int rem = s_rem;
        __syncthreads();
        if (rem == 0) break;
    }
    g_ft[b * VV + v] = myft;

    // t_last = max activation time among activated codes (0 if none)
    s_red[v] = (myft < TT) ? myft : 0;
    __syncthreads();
#pragma unroll
    for (int s = VV / 2; s > 0; s >>= 1) {
        if (v < s) s_red[v] = max(s_red[v], s_red[v + s]);
        __syncthreads();
    }
    if (v == 0) g_tlast[b] = s_red[0];
}

// ---------------------------------------------------------------------------
// Kernel 2: transpose W (row-major [V,V], W[u,v]) into Wt[v,u].
// ---------------------------------------------------------------------------
__global__ void transpose_w(const float* __restrict__ W) {
    __shared__ float tile[32][33];
    int x = blockIdx.x * 32 + threadIdx.x;   // v
    int y = blockIdx.y * 32 + threadIdx.y;   // u base
#pragma unroll
    for (int j = 0; j < 32; j += 8)
        tile[threadIdx.y + j][threadIdx.x] = W[(size_t)(y + j) * VV + x];
    __syncthreads();
    x = blockIdx.y * 32 + threadIdx.x;       // u
    y = blockIdx.x * 32 + threadIdx.y;       // v base
#pragma unroll
    for (int j = 0; j < 32; j += 8)
        g_Wt[(size_t)(y + j) * VV + x] = tile[threadIdx.x][threadIdx.y + j];
}

// ---------------------------------------------------------------------------
// Kernel 3: per-batch chunk-boundary states + steady-state row S.
// Grid: BB blocks x VV threads (thread u owns one logit lane).
// ---------------------------------------------------------------------------
__global__ void boundary_states(const float* __restrict__ bias) {
    const int b = blockIdx.x;
    const int u = threadIdx.x;

    __shared__ int s_list[VV];
    __shared__ int s_cnt;

    const int myft = g_ft[b * VV + u];   // thread u doubles as scanner of code u
    float L = bias[u];

    for (int c = 0; c < NCHUNK; c++) {
        g_states[((size_t)b * NCHUNK + c) * VV + u] = L;

        if (u == 0) s_cnt = 0;
        __syncthreads();
        if (myft >= c * CHUNK && myft < (c + 1) * CHUNK) {
            int idx = atomicAdd(&s_cnt, 1);
            s_list[idx] = u;
        }
        __syncthreads();
        const int cnt = s_cnt;

        int i = 0;
        for (; i + 8 <= cnt; i += 8) {
            float w0 = g_Wt[s_list[i + 0] * VV + u];
            float w1 = g_Wt[s_list[i + 1] * VV + u];
            float w2 = g_Wt[s_list[i + 2] * VV + u];
            float w3 = g_Wt[s_list[i + 3] * VV + u];
            float w4 = g_Wt[s_list[i + 4] * VV + u];
            float w5 = g_Wt[s_list[i + 5] * VV + u];
            float w6 = g_Wt[s_list[i + 6] * VV + u];
            float w7 = g_Wt[s_list[i + 7] * VV + u];
            L += ((w0 + w1) + (w2 + w3)) + ((w4 + w5) + (w6 + w7));
        }
        for (; i < cnt; i++) L += g_Wt[s_list[i] * VV + u];
        __syncthreads();   // protect s_cnt/s_list reuse next chunk
    }
    g_S[b * VV + u] = L;   // includes every activated code
}

// ---------------------------------------------------------------------------
// Kernel 4: varying-region emit: rows t in [0, vend), vend = min(t_last, limit).
// Grid: (NCHUNK, BB) x 128 threads; CTAs past vend exit immediately.
// ---------------------------------------------------------------------------
__global__ void varying_emit(const int* __restrict__ lengths, float* __restrict__ out) {
    const int c   = blockIdx.x;
    const int b   = blockIdx.y;
    const int tid = threadIdx.x;           // 0..127 == CHUNK
    const int t0  = c * CHUNK;

    const int limit = lengths[b] - 1;
    const int vend  = min(g_tlast[b], limit);
    if (t0 >= vend) return;
    const int ve = min(min(t0 + CHUNK, TM1), vend);   // rows [t0, ve)

    __shared__ int s_cnt[CHUNK];
    __shared__ int s_off[CHUNK + 1];
    __shared__ int s_list[VV];
    __shared__ int s_time[VV];

    s_cnt[tid] = 0;
    __syncthreads();

#pragma unroll
    for (int k = 0; k < 4; k++) {
        int v = k * CHUNK + tid;
        int f = g_ft[b * VV + v];
        if (f >= t0 && f < t0 + CHUNK) atomicAdd(&s_cnt[f - t0], 1);
    }
    __syncthreads();
    if (tid == 0) {
        int acc = 0;
        for (int i = 0; i < CHUNK; i++) { s_off[i] = acc; acc += s_cnt[i]; }
        s_off[CHUNK] = acc;
    }
    __syncthreads();
    s_cnt[tid] = s_off[tid];
    __syncthreads();
#pragma unroll
    for (int k = 0; k < 4; k++) {
        int v = k * CHUNK + tid;
        int f = g_ft[b * VV + v];
        if (f >= t0 && f < t0 + CHUNK) {
            int idx = atomicAdd(&s_cnt[f - t0], 1);
            s_list[idx] = v;
            s_time[idx] = f;
        }
    }
    __syncthreads();

    float4 L = ((const float4*)(g_states + ((size_t)b * NCHUNK + c) * VV))[tid];
    const int cnt = s_off[CHUNK];
    float4* obase = (float4*)out + (size_t)b * TM1 * (VV / 4) + tid;

    const int D = 8;
    float4 buf[D];
#pragma unroll
    for (int j = 0; j < D; j++)
        if (j < cnt) buf[j] = ((const float4*)(g_Wt + (size_t)s_list[j] * VV))[tid];

    int wt = t0;
    for (int i = 0; i < cnt; i++) {
        int ti = s_time[i];
        if (ti >= ve) break;
        while (wt < ti) { obase[(size_t)wt * (VV / 4)] = L; wt++; }
        float4 w = buf[i & (D - 1)];
        L.x += w.x; L.y += w.y; L.z += w.z; L.w += w.w;
        if (i + D < cnt)
            buf[i & (D - 1)] = ((const float4*)(g_Wt + (size_t)s_list[i + D] * VV))[tid];
    }
    while (wt < ve) { obase[(size_t)wt * (VV / 4)] = L; wt++; }
}

// ---------------------------------------------------------------------------
// Kernel 5: constant-region fill: rows t in [vend, TM1).
//   t <  limit : write steady-state row S_b
//   t >= limit : write zeros (d_out is poisoned)
// Grid: (FILLG, BB) x 256 threads. Thread = float4 lane (tid&127), row parity
// (tid>>7). Fully independent unrolled stores -> maximum write MLP.
// ---------------------------------------------------------------------------
__global__ void fill(const int* __restrict__ lengths, float* __restrict__ out) {
    const int b     = blockIdx.y;
    const int limit = lengths[b] - 1;
    const int vend  = min(g_tlast[b], limit);

    const int total = TM1 - vend;
    if (total <= 0) return;
    const int per = (total + FILLG - 1) / FILLG;
    const int r0  = vend + blockIdx.x * per;
    const int r1  = min(r0 + per, TM1);
    if (r0 >= r1) return;

    const int lane = threadIdx.x & 127;
    const int sub  = threadIdx.x >> 7;     // 0 or 1

    const float4 S = ((const float4*)(g_S + (size_t)b * VV))[lane];
    const float4 Z = make_float4(0.f, 0.f, 0.f, 0.f);
    float4* obase = (float4*)out + (size_t)b * TM1 * (VV / 4) + lane;

    int t = r0 + sub;
#pragma unroll 8
    for (; t < r1; t += 2) {
        float4 val = (t < limit) ? S : Z;
        obase[(size_t)t * (VV / 4)] = val;
    }
}

// ---------------------------------------------------------------------------
// Launch: inputs (metadata order): times[B,T] f32, codes[B,T,V] f32,
// lengths[B] i32, W[V,V] f32, b[V] f32. Output: [B, T-1, V] f32.
// ---------------------------------------------------------------------------
extern "C" void kernel_launch(void* const* d_in, const int* in_sizes, int n_in,
                              void* d_out, int out_size) {
    const float* codes   = (const float*)d_in[1];
    const int*   lengths = (const int*)d_in[2];
    const float* W       = (const float*)d_in[3];
    const float* bias    = (const float*)d_in[4];
    float*       out     = (float*)d_out;

    find_first<<<BB, VV>>>(codes);
    transpose_w<<<dim3(VV / 32, VV / 32), dim3(32, 8)>>>(W);
    boundary_states<<<BB, VV>>>(bias);
    fill<<<dim3(FILLG, BB), 256>>>(lengths, out);
    varying_emit<<<dim3(NCHUNK, BB), CHUNK>>>(lengths, out);
}

// round 3
// speedup vs baseline: 1.5688x; 1.5688x over previous
#include <cuda_runtime.h>
#include <cuda_bf16.h>

// Problem shape (LogRegBaseline): B=64, T=2048, V=512
#define BB     64
#define TT     2048
#define VV     512
#define TM1    (TT - 1)          // 2047 output positions
#define CH2    32                // time positions per varying-emit chunk
#define NC2    64                // 64*32 = 2048 covers all activation times
#define FILLG  18                // fill row-groups per batch

// Scratch (device globals; no allocation allowed)
__device__ int   g_ft[BB * VV];               // first-activation time per (b,v); TT if never
__device__ int   g_tlast[BB];                 // max activation time per batch (0 if none)
__device__ float g_Wt[VV * VV];               // W transposed: Wt[v*VV+u] = W[u*VV+v]
__device__ float g_states[BB * NC2 * VV];     // prefix logits at each 32-row chunk boundary (8MB)
__device__ float g_S[BB * VV];                // steady-state row

// ---------------------------------------------------------------------------
// Kernel 1: first activation time per (b,v) + block-max t_last.
// Grid: BB x VV. 16-wide t-scan, collective early exit (two-barrier pattern).
// ---------------------------------------------------------------------------
__global__ void find_first(const float* __restrict__ codes) {
    const int b = blockIdx.x;
    const int v = threadIdx.x;
    __shared__ int s_rem;
    __shared__ int s_red[VV];
    if (v == 0) s_rem = VV;
    __syncthreads();

    const float* p = codes + (size_t)b * TT * VV + v;
    int  myft  = TT;
    bool found = false;

    for (int t0 = 0; t0 < TT; t0 += 16) {
        if (!found) {
            float x[16];
#pragma unroll
            for (int k = 0; k < 16; k++) x[k] = p[(size_t)(t0 + k) * VV];
#pragma unroll
            for (int k = 0; k < 16; k++) {
                if (!found && x[k] != 0.0f) { found = true; myft = t0 + k; }
            }
            if (found) atomicAdd(&s_rem, -1);
        }
        __syncthreads();
        int rem = s_rem;     // decrements for this iter are pre-barrier
        __syncthreads();     // nobody issues next-iter atomics before all read
        if (rem == 0) break;
    }
    g_ft[b * VV + v] = myft;

    s_red[v] = (myft < TT) ? myft : 0;
    __syncthreads();
#pragma unroll
    for (int s = VV / 2; s > 0; s >>= 1) {
        if (v < s) s_red[v] = max(s_red[v], s_red[v + s]);
        __syncthreads();
    }
    if (v == 0) g_tlast[b] = s_red[0];
}

// ---------------------------------------------------------------------------
// Kernel 2: transpose W[u,v] -> Wt[v,u].
// ---------------------------------------------------------------------------
__global__ void transpose_w(const float* __restrict__ W) {
    __shared__ float tile[32][33];
    int x = blockIdx.x * 32 + threadIdx.x;
    int y = blockIdx.y * 32 + threadIdx.y;
#pragma unroll
    for (int j = 0; j < 32; j += 8)
        tile[threadIdx.y + j][threadIdx.x] = W[(size_t)(y + j) * VV + x];
    __syncthreads();
    x = blockIdx.y * 32 + threadIdx.x;
    y = blockIdx.x * 32 + threadIdx.y;
#pragma unroll
    for (int j = 0; j < 32; j += 8)
        g_Wt[(size_t)(y + j) * VV + x] = tile[threadIdx.x][threadIdx.y + j];
}

// ---------------------------------------------------------------------------
// Kernel 3: per-batch chunk-boundary states (every 32 rows) + steady row S.
// Grid: BB x VV. Lists for ALL 64 chunks built once via bucket sort; the
// accumulate loop then runs barrier-free per thread.
// ---------------------------------------------------------------------------
__global__ void boundary_states(const float* __restrict__ bias) {
    const int b = blockIdx.x;
    const int u = threadIdx.x;

    __shared__ int s_bcnt[NC2];     // per-chunk counts, then scatter cursors
    __shared__ int s_boff[NC2 + 1];
    __shared__ int s_list[VV];      // v's grouped by chunk

    const int myft = g_ft[b * VV + u];
    const int myc  = (myft < TT) ? (myft >> 5) : -1;

    if (u < NC2) s_bcnt[u] = 0;
    __syncthreads();
    if (myc >= 0) atomicAdd(&s_bcnt[myc], 1);
    __syncthreads();
    if (u == 0) {
        int acc = 0;
        for (int c = 0; c < NC2; c++) { s_boff[c] = acc; acc += s_bcnt[c]; }
        s_boff[NC2] = acc;
    }
    __syncthreads();
    if (u < NC2) s_bcnt[u] = s_boff[u];   // cursors
    __syncthreads();
    if (myc >= 0) {
        int idx = atomicAdd(&s_bcnt[myc], 1);
        s_list[idx] = u;
    }
    __syncthreads();

    float L = bias[u];
    int i = 0;
    for (int c = 0; c < NC2; c++) {
        g_states[((size_t)b * NC2 + c) * VV + u] = L;
        const int e = s_boff[c + 1];
        for (; i + 8 <= e; i += 8) {
            float w0 = g_Wt[s_list[i + 0] * VV + u];
            float w1 = g_Wt[s_list[i + 1] * VV + u];
            float w2 = g_Wt[s_list[i + 2] * VV + u];
            float w3 = g_Wt[s_list[i + 3] * VV + u];
            float w4 = g_Wt[s_list[i + 4] * VV + u];
            float w5 = g_Wt[s_list[i + 5] * VV + u];
            float w6 = g_Wt[s_list[i + 6] * VV + u];
            float w7 = g_Wt[s_list[i + 7] * VV + u];
            L += ((w0 + w1) + (w2 + w3)) + ((w4 + w5) + (w6 + w7));
        }
        for (; i < e; i++) L += g_Wt[s_list[i] * VV + u];
    }
    g_S[b * VV + u] = L;
}

// ---------------------------------------------------------------------------
// Kernel 4: constant-region fill: rows t in [vend, TM1).
//   t < limit : steady row S_b ; t >= limit : zeros.
// Grid (FILLG, BB) x 512. Thread = float4 lane (tid&127), row phase (tid>>7).
// Streaming stores (__stcs): write-once data.
// ---------------------------------------------------------------------------
__global__ void fill(const int* __restrict__ lengths, float* __restrict__ out) {
    const int b     = blockIdx.y;
    const int limit = lengths[b] - 1;
    const int vend  = min(g_tlast[b], limit);

    const int total = TM1 - vend;
    if (total <= 0) return;
    const int per = (total + FILLG - 1) / FILLG;
    const int r0  = vend + blockIdx.x * per;
    const int r1  = min(r0 + per, TM1);
    if (r0 >= r1) return;

    const int lane = threadIdx.x & 127;
    const int sub  = threadIdx.x >> 7;     // 0..3

    const float4 S = ((const float4*)(g_S + (size_t)b * VV))[lane];
    const float4 Z = make_float4(0.f, 0.f, 0.f, 0.f);
    float4* obase = (float4*)out + (size_t)b * TM1 * (VV / 4) + lane;

    int t = r0 + sub;
#pragma unroll 8
    for (; t < r1; t += 4) {
        float4 val = (t < limit) ? S : Z;
        __stcs(&obase[(size_t)t * (VV / 4)], val);
    }
}

// ---------------------------------------------------------------------------
// Kernel 5: varying-region emit: rows t in [0, vend), vend = min(t_last,limit).
// Grid (NC2, BB) x 128. Activations bucket-sorted by t within the 32-row
// chunk; add/store sweep with STATIC 8-deep register prefetch (no dynamic
// register indexing -> no local-memory demotion).
// ---------------------------------------------------------------------------
__global__ void varying_emit(const int* __restrict__ lengths, float* __restrict__ out) {
    const int c   = blockIdx.x;
    const int b   = blockIdx.y;
    const int tid = threadIdx.x;           // 0..127, float4 lane
    const int t0  = c * CH2;

    const int limit = lengths[b] - 1;
    const int vend  = min(g_tlast[b], limit);
    if (t0 >= vend) return;
    const int ve = min(min(t0 + CH2, TM1), vend);   // store rows [t0, ve)

    __shared__ int s_cnt[CH2];
    __shared__ int s_off[CH2 + 1];
    __shared__ int s_list[VV];
    __shared__ int s_time[VV];

    if (tid < CH2) s_cnt[tid] = 0;
    __syncthreads();

#pragma unroll
    for (int k = 0; k < 4; k++) {
        int v = k * 128 + tid;
        int f = g_ft[b * VV + v];
        if (f >= t0 && f < t0 + CH2) atomicAdd(&s_cnt[f - t0], 1);
    }
    __syncthreads();
    if (tid == 0) {
        int acc = 0;
        for (int i = 0; i < CH2; i++) { s_off[i] = acc; acc += s_cnt[i]; }
        s_off[CH2] = acc;
    }
    __syncthreads();
    if (tid < CH2) s_cnt[tid] = s_off[tid];   // cursors
    __syncthreads();
#pragma unroll
    for (int k = 0; k < 4; k++) {
        int v = k * 128 + tid;
        int f = g_ft[b * VV + v];
        if (f >= t0 && f < t0 + CH2) {
            int idx = atomicAdd(&s_cnt[f - t0], 1);
            s_list[idx] = v;
            s_time[idx] = f;
        }
    }
    __syncthreads();

    float4 L = ((const float4*)(g_states + ((size_t)b * NC2 + c) * VV))[tid];
    const int cnt = s_off[CH2];
    float4* obase = (float4*)out + (size_t)b * TM1 * (VV / 4) + tid;

    // Static 8-deep prefetch pipeline over Wt columns (w[] stays in registers)
    float4 w[8];
#pragma unroll
    for (int k = 0; k < 8; k++)
        w[k] = (k < cnt) ? ((const float4*)(g_Wt + (size_t)s_list[k] * VV))[tid]
                         : make_float4(0.f, 0.f, 0.f, 0.f);

    int wt = t0;
    for (int base = 0; base < cnt; base += 8) {
#pragma unroll
        for (int k = 0; k < 8; k++) {
            const int i = base + k;
            if (i < cnt) {
                const int te = min(s_time[i], ve);
                while (wt < te) { __stcs(&obase[(size_t)wt * (VV / 4)], L); wt++; }
                L.x += w[k].x; L.y += w[k].y; L.z += w[k].z; L.w += w[k].w;
                const int j = i + 8;
                if (j < cnt)
                    w[k] = ((const float4*)(g_Wt + (size_t)s_list[j] * VV))[tid];
            }
        }
    }
    while (wt < ve) { __stcs(&obase[(size_t)wt * (VV / 4)], L); wt++; }
}

// ---------------------------------------------------------------------------
// Launch. Inputs (metadata order): times[B,T] f32, codes[B,T,V] f32,
// lengths[B] i32, W[V,V] f32, b[V] f32. Output: [B, T-1, V] f32.
// ---------------------------------------------------------------------------
extern "C" void kernel_launch(void* const* d_in, const int* in_sizes, int n_in,
                              void* d_out, int out_size) {
    const float* codes   = (const float*)d_in[1];
    const int*   lengths = (const int*)d_in[2];
    const float* W       = (const float*)d_in[3];
    const float* bias    = (const float*)d_in[4];
    float*       out     = (float*)d_out;

    find_first<<<BB, VV>>>(codes);
    transpose_w<<<dim3(VV / 32, VV / 32), dim3(32, 8)>>>(W);
    boundary_states<<<BB, VV>>>(bias);
    fill<<<dim3(FILLG, BB), 512>>>(lengths, out);
    varying_emit<<<dim3(NC2, BB), 128>>>(lengths, out);
}

// round 4
// speedup vs baseline: 1.6977x; 1.0822x over previous
#include <cuda_runtime.h>
#include <cuda_bf16.h>

// Problem shape (LogRegBaseline): B=64, T=2048, V=512
#define BB     64
#define TT     2048
#define VV     512
#define TM1    (TT - 1)          // 2047 output positions
#define CH2    32                // time positions per varying chunk
#define NC2    64                // 64*32 = 2048 covers all activation times
#define FILLG2 72                // fill slices per batch (128-thread CTAs)

// Scratch (device globals; no allocation allowed)
__device__ int   g_ft[BB * VV];               // first-activation time per (b,v); TT if never
__device__ int   g_tlast[BB];                 // max activation time per batch (0 if none)
__device__ float g_Wt[VV * VV];               // W transposed: Wt[v*VV+u] = W[u*VV+v]
__device__ float g_states[BB * NC2 * VV];     // prefix logits at each 32-row chunk boundary
__device__ float g_S[BB * VV];                // steady-state row

// ---------------------------------------------------------------------------
// Kernel 1: transpose W[u,v] -> Wt[v,u].
// ---------------------------------------------------------------------------
__global__ void transpose_w(const float* __restrict__ W) {
    __shared__ float tile[32][33];
    int x = blockIdx.x * 32 + threadIdx.x;
    int y = blockIdx.y * 32 + threadIdx.y;
#pragma unroll
    for (int j = 0; j < 32; j += 8)
        tile[threadIdx.y + j][threadIdx.x] = W[(size_t)(y + j) * VV + x];
    __syncthreads();
    x = blockIdx.y * 32 + threadIdx.x;
    y = blockIdx.x * 32 + threadIdx.y;
#pragma unroll
    for (int j = 0; j < 32; j += 8)
        g_Wt[(size_t)(y + j) * VV + x] = tile[threadIdx.x][threadIdx.y + j];
}

// ---------------------------------------------------------------------------
// Kernel 2 (fused prep): per batch b (64 CTAs x 512 threads):
//   a) per-thread first-activation scan (stops at OWN ft; no block barriers)
//   b) block-max t_last
//   c) bucket-sort activations by 32-row chunk
//   d) chunk-boundary prefix states + steady-state row S
// ---------------------------------------------------------------------------
__global__ void prep(const float* __restrict__ codes, const float* __restrict__ bias) {
    const int b = blockIdx.x;
    const int v = threadIdx.x;          // doubles as logit lane u

    __shared__ int s_red[VV];
    __shared__ int s_bcnt[NC2];
    __shared__ int s_boff[NC2 + 1];
    __shared__ int s_list[VV];

    // a) scan until own first activation (16-blocked loads for MLP)
    const float* p = codes + (size_t)b * TT * VV + v;
    int myft = TT;
    for (int t0 = 0; t0 < TT; t0 += 16) {
        float x[16];
#pragma unroll
        for (int k = 0; k < 16; k++) x[k] = p[(size_t)(t0 + k) * VV];
        bool hit = false;
#pragma unroll
        for (int k = 0; k < 16; k++) {
            if (!hit && x[k] != 0.0f) { hit = true; myft = t0 + k; }
        }
        if (hit) break;
    }
    g_ft[b * VV + v] = myft;

    // b) t_last = max activation time (0 if none)
    s_red[v] = (myft < TT) ? myft : 0;
    __syncthreads();
#pragma unroll
    for (int s = VV / 2; s > 0; s >>= 1) {
        if (v < s) s_red[v] = max(s_red[v], s_red[v + s]);
        __syncthreads();
    }
    if (v == 0) g_tlast[b] = s_red[0];

    // c) bucket sort by chunk
    const int myc = (myft < TT) ? (myft >> 5) : -1;
    if (v < NC2) s_bcnt[v] = 0;
    __syncthreads();
    if (myc >= 0) atomicAdd(&s_bcnt[myc], 1);
    __syncthreads();
    if (v == 0) {
        int acc = 0;
        for (int c = 0; c < NC2; c++) { s_boff[c] = acc; acc += s_bcnt[c]; }
        s_boff[NC2] = acc;
    }
    __syncthreads();
    if (v < NC2) s_bcnt[v] = s_boff[v];   // cursors
    __syncthreads();
    if (myc >= 0) {
        int idx = atomicAdd(&s_bcnt[myc], 1);
        s_list[idx] = v;
    }
    __syncthreads();

    // d) boundary states + steady row (8-wide batched column loads)
    float L = bias[v];
    int i = 0;
    for (int c = 0; c < NC2; c++) {
        g_states[((size_t)b * NC2 + c) * VV + v] = L;
        const int e = s_boff[c + 1];
        for (; i + 8 <= e; i += 8) {
            float w0 = g_Wt[s_list[i + 0] * VV + v];
            float w1 = g_Wt[s_list[i + 1] * VV + v];
            float w2 = g_Wt[s_list[i + 2] * VV + v];
            float w3 = g_Wt[s_list[i + 3] * VV + v];
            float w4 = g_Wt[s_list[i + 4] * VV + v];
            float w5 = g_Wt[s_list[i + 5] * VV + v];
            float w6 = g_Wt[s_list[i + 6] * VV + v];
            float w7 = g_Wt[s_list[i + 7] * VV + v];
            L += ((w0 + w1) + (w2 + w3)) + ((w4 + w5) + (w6 + w7));
        }
        for (; i < e; i++) L += g_Wt[s_list[i] * VV + v];
    }
    g_S[b * VV + v] = L;
}

// ---------------------------------------------------------------------------
// Kernel 3 (fused output), grid (NC2 + FILLG2, BB) x 128 threads:
//   blockIdx.x <  NC2 : varying-region chunk (rows [t0, min(t0+32, vend)))
//   blockIdx.x >= NC2 : constant-region fill slice (rows [vend, TM1))
// vend = min(t_last, limit); t >= limit rows are zeros.
// ---------------------------------------------------------------------------
__global__ void output_k(const int* __restrict__ lengths, float* __restrict__ out) {
    const int b   = blockIdx.y;
    const int tid = threadIdx.x;           // 0..127, float4 lane
    const int limit = lengths[b] - 1;
    const int vend  = min(g_tlast[b], limit);

    float4* obase = (float4*)out + (size_t)b * TM1 * (VV / 4) + tid;

    if (blockIdx.x >= NC2) {
        // ---- fill slice ----
        const int slice = blockIdx.x - NC2;
        const int total = TM1 - vend;
        if (total <= 0) return;
        const int per = (total + FILLG2 - 1) / FILLG2;
        const int r0  = vend + slice * per;
        const int r1  = min(r0 + per, TM1);
        if (r0 >= r1) return;

        const float4 S = ((const float4*)(g_S + (size_t)b * VV))[tid];
        const float4 Z = make_float4(0.f, 0.f, 0.f, 0.f);
#pragma unroll 8
        for (int t = r0; t < r1; t++) {
            float4 val = (t < limit) ? S : Z;
            __stcs(&obase[(size_t)t * (VV / 4)], val);
        }
        return;
    }

    // ---- varying chunk ----
    const int c  = blockIdx.x;
    const int t0 = c * CH2;
    if (t0 >= vend) return;
    const int ve = min(min(t0 + CH2, TM1), vend);

    __shared__ int s_cnt[CH2];
    __shared__ int s_off[CH2 + 1];
    __shared__ int s_list[VV];
    __shared__ int s_time[VV];

    if (tid < CH2) s_cnt[tid] = 0;
    __syncthreads();
#pragma unroll
    for (int k = 0; k < 4; k++) {
        int v = k * 128 + tid;
        int f = g_ft[b * VV + v];
        if (f >= t0 && f < t0 + CH2) atomicAdd(&s_cnt[f - t0], 1);
    }
    __syncthreads();
    if (tid == 0) {
        int acc = 0;
        for (int i = 0; i < CH2; i++) { s_off[i] = acc; acc += s_cnt[i]; }
        s_off[CH2] = acc;
    }
    __syncthreads();
    if (tid < CH2) s_cnt[tid] = s_off[tid];   // cursors
    __syncthreads();
#pragma unroll
    for (int k = 0; k < 4; k++) {
        int v = k * 128 + tid;
        int f = g_ft[b * VV + v];
        if (f >= t0 && f < t0 + CH2) {
            int idx = atomicAdd(&s_cnt[f - t0], 1);
            s_list[idx] = v;
            s_time[idx] = f;
        }
    }
    __syncthreads();

    float4 L = ((const float4*)(g_states + ((size_t)b * NC2 + c) * VV))[tid];
    const int cnt = s_off[CH2];

    // Static 8-deep register prefetch over Wt columns (no dynamic reg indexing)
    float4 w[8];
#pragma unroll
    for (int k = 0; k < 8; k++)
        w[k] = (k < cnt) ? ((const float4*)(g_Wt + (size_t)s_list[k] * VV))[tid]
                         : make_float4(0.f, 0.f, 0.f, 0.f);

    int wt = t0;
    for (int base = 0; base < cnt; base += 8) {
#pragma unroll
        for (int k = 0; k < 8; k++) {
            const int i = base + k;
            if (i < cnt) {
                const int te = min(s_time[i], ve);
                while (wt < te) { __stcs(&obase[(size_t)wt * (VV / 4)], L); wt++; }
                L.x += w[k].x; L.y += w[k].y; L.z += w[k].z; L.w += w[k].w;
                const int j = i + 8;
                if (j < cnt)
                    w[k] = ((const float4*)(g_Wt + (size_t)s_list[j] * VV))[tid];
            }
        }
    }
    while (wt < ve) { __stcs(&obase[(size_t)wt * (VV / 4)], L); wt++; }
}

// ---------------------------------------------------------------------------
// Launch. Inputs (metadata order): times[B,T] f32, codes[B,T,V] f32,
// lengths[B] i32, W[V,V] f32, b[V] f32. Output: [B, T-1, V] f32.
// ---------------------------------------------------------------------------
extern "C" void kernel_launch(void* const* d_in, const int* in_sizes, int n_in,
                              void* d_out, int out_size) {
    const float* codes   = (const float*)d_in[1];
    const int*   lengths = (const int*)d_in[2];
    const float* W       = (const float*)d_in[3];
    const float* bias    = (const float*)d_in[4];
    float*       out     = (float*)d_out;

    transpose_w<<<dim3(VV / 32, VV / 32), dim3(32, 8)>>>(W);
    prep<<<BB, VV>>>(codes, bias);
    output_k<<<dim3(NC2 + FILLG2, BB), 128>>>(lengths, out);
}

// round 5
// speedup vs baseline: 3.4818x; 2.0509x over previous
#include <cuda_runtime.h>
#include <cuda_bf16.h>

// Problem shape (LogRegBaseline): B=64, T=2048, V=512
#define BB    64
#define TT    2048
#define VV    512
#define TM1   (TT - 1)           // 2047 output positions
#define NSEG  8                  // activation-index segments per batch
#define SEG   64                 // activations per segment (NSEG*SEG = VV)
#define FILLG 96                 // fill slices per batch

// Scratch (device globals; no allocation allowed)
__device__ int   g_ft[BB * VV];          // first-activation time per (b,v); TT if never
__device__ int   g_tlast[BB];            // max activation time per batch (0 if none)
__device__ int   g_alist[BB * VV];       // activation v's sorted by time
__device__ int   g_atime[BB * VV];       // matching sorted times
__device__ int   g_acnt[BB];             // number of activations per batch
__device__ float g_Wt[VV * VV];          // W transposed: Wt[v*VV+u] = W[u*VV+v]
__device__ float g_seg[BB * NSEG * VV];      // per-segment column sums
__device__ float g_segstate[BB * NSEG * VV]; // exclusive prefix: state at segment start
__device__ float g_S[BB * VV];           // steady-state row (bias + all activations)

// ---------------------------------------------------------------------------
// Kernel 1: transpose W[u,v] -> Wt[v,u].
// ---------------------------------------------------------------------------
__global__ void transpose_w(const float* __restrict__ W) {
    __shared__ float tile[32][33];
    int x = blockIdx.x * 32 + threadIdx.x;
    int y = blockIdx.y * 32 + threadIdx.y;
#pragma unroll
    for (int j = 0; j < 32; j += 8)
        tile[threadIdx.y + j][threadIdx.x] = W[(size_t)(y + j) * VV + x];
    __syncthreads();
    x = blockIdx.y * 32 + threadIdx.x;
    y = blockIdx.x * 32 + threadIdx.y;
#pragma unroll
    for (int j = 0; j < 32; j += 8)
        g_Wt[(size_t)(y + j) * VV + x] = tile[threadIdx.x][threadIdx.y + j];
}

// ---------------------------------------------------------------------------
// Kernel 2: per-(b,v) first-activation scan, early exit at own ft.
// Grid (BB, 4) x 128: 256 CTAs spread across SMs.
// ---------------------------------------------------------------------------
__global__ void scan_ft(const float* __restrict__ codes) {
    const int b = blockIdx.x;
    const int v = blockIdx.y * 128 + threadIdx.x;
    const float* p = codes + (size_t)b * TT * VV + v;
    int myft = TT;
    for (int t0 = 0; t0 < TT; t0 += 16) {
        float x[16];
#pragma unroll
        for (int k = 0; k < 16; k++) x[k] = p[(size_t)(t0 + k) * VV];
        bool hit = false;
#pragma unroll
        for (int k = 0; k < 16; k++) {
            if (!hit && x[k] != 0.0f) { hit = true; myft = t0 + k; }
        }
        if (hit) break;
    }
    g_ft[b * VV + v] = myft;
}

// ---------------------------------------------------------------------------
// Kernel 3: per-batch exact counting sort of activations by time + t_last.
// Grid BB x 512. 2048 smem buckets, Hillis-Steele block scan.
// ---------------------------------------------------------------------------
__global__ void sort_acts() {
    const int b   = blockIdx.x;
    const int tid = threadIdx.x;
    __shared__ int cnt[TT];      // 8KB buckets -> cursors
    __shared__ int s4[VV];       // scan workspace
    __shared__ int red[VV];      // max-reduce workspace

    const int myft = g_ft[b * VV + tid];

    // t_last
    red[tid] = (myft < TT) ? myft : 0;
    __syncthreads();
#pragma unroll
    for (int s = VV / 2; s > 0; s >>= 1) {
        if (tid < s) red[tid] = max(red[tid], red[tid + s]);
        __syncthreads();
    }
    if (tid == 0) g_tlast[b] = red[0];

    // counting sort
#pragma unroll
    for (int k = 0; k < 4; k++) cnt[k * VV + tid] = 0;
    __syncthreads();
    if (myft < TT) atomicAdd(&cnt[myft], 1);
    __syncthreads();

    const int a0 = cnt[4 * tid], a1 = cnt[4 * tid + 1];
    const int a2 = cnt[4 * tid + 2], a3 = cnt[4 * tid + 3];
    const int mysum = a0 + a1 + a2 + a3;
    s4[tid] = mysum;
    __syncthreads();
    for (int d = 1; d < VV; d <<= 1) {       // inclusive Hillis-Steele
        int val = (tid >= d) ? s4[tid - d] : 0;
        __syncthreads();
        s4[tid] += val;
        __syncthreads();
    }
    const int ex = s4[tid] - mysum;          // exclusive
    cnt[4 * tid]     = ex;
    cnt[4 * tid + 1] = ex + a0;
    cnt[4 * tid + 2] = ex + a0 + a1;
    cnt[4 * tid + 3] = ex + a0 + a1 + a2;
    if (tid == VV - 1) g_acnt[b] = s4[VV - 1];
    __syncthreads();

    if (myft < TT) {
        int pos = atomicAdd(&cnt[myft], 1);
        g_alist[b * VV + pos] = tid;
        g_atime[b * VV + pos] = myft;
    }
}

// ---------------------------------------------------------------------------
// Kernel 4: per-segment column sums (PARALLEL over the old serial chain).
// Grid (NSEG, BB) x 512 (thread = logit lane u).
// ---------------------------------------------------------------------------
__global__ void segsum() {
    const int s = blockIdx.x;
    const int b = blockIdx.y;
    const int u = threadIdx.x;
    __shared__ int sl[SEG];

    const int A  = g_acnt[b];
    const int i0 = s * SEG;
    const int i1 = min(i0 + SEG, A);
    const int n  = max(i1 - i0, 0);

    if (u < SEG && u < n) sl[u] = g_alist[b * VV + i0 + u];
    __syncthreads();

    float acc = 0.0f;
    int i = 0;
    for (; i + 8 <= n; i += 8) {
        float w0 = g_Wt[sl[i + 0] * VV + u];
        float w1 = g_Wt[sl[i + 1] * VV + u];
        float w2 = g_Wt[sl[i + 2] * VV + u];
        float w3 = g_Wt[sl[i + 3] * VV + u];
        float w4 = g_Wt[sl[i + 4] * VV + u];
        float w5 = g_Wt[sl[i + 5] * VV + u];
        float w6 = g_Wt[sl[i + 6] * VV + u];
        float w7 = g_Wt[sl[i + 7] * VV + u];
        acc += ((w0 + w1) + (w2 + w3)) + ((w4 + w5) + (w6 + w7));
    }
    for (; i < n; i++) acc += g_Wt[sl[i] * VV + u];

    g_seg[((size_t)b * NSEG + s) * VV + u] = acc;
}

// ---------------------------------------------------------------------------
// Kernel 5: exclusive prefix over 8 segments -> segment-start states + S.
// Grid BB x 512.
// ---------------------------------------------------------------------------
__global__ void segprefix(const float* __restrict__ bias) {
    const int b = blockIdx.x;
    const int u = threadIdx.x;
    float sg[NSEG];
#pragma unroll
    for (int s = 0; s < NSEG; s++) sg[s] = g_seg[((size_t)b * NSEG + s) * VV + u];
    float run = bias[u];
#pragma unroll
    for (int s = 0; s < NSEG; s++) {
        g_segstate[((size_t)b * NSEG + s) * VV + u] = run;
        run += sg[s];
    }
    g_S[b * VV + u] = run;
}

// ---------------------------------------------------------------------------
// Kernel 6 (fused output), grid (FILLG + NSEG, BB) x 128 threads:
//   blockIdx.x <  FILLG : constant-region fill slice, rows [vend, TM1)
//   blockIdx.x >= FILLG : varying segment s, rows between its sorted
//                         activation times, starting from g_segstate[s].
// vend = min(t_last, limit); rows t >= limit are zeros.
// ---------------------------------------------------------------------------
__global__ void output_k(const int* __restrict__ lengths, float* __restrict__ out) {
    const int b     = blockIdx.y;
    const int tid   = threadIdx.x;          // float4 lane
    const int limit = lengths[b] - 1;
    const int vend  = min(g_tlast[b], limit);

    float4* obase = (float4*)out + (size_t)b * TM1 * (VV / 4) + tid;

    if (blockIdx.x < FILLG) {
        // ---- fill slice (gets the low bids: long pole launches first) ----
        const int total = TM1 - vend;
        if (total <= 0) return;
        const int per = (total + FILLG - 1) / FILLG;
        const int r0  = vend + blockIdx.x * per;
        const int r1  = min(r0 + per, TM1);
        if (r0 >= r1) return;

        const float4 S = ((const float4*)(g_S + (size_t)b * VV))[tid];
        const float4 Z = make_float4(0.f, 0.f, 0.f, 0.f);
#pragma unroll 8
        for (int t = r0; t < r1; t++) {
            float4 val = (t < limit) ? S : Z;
            __stcs(&obase[(size_t)t * (VV / 4)], val);
        }
        return;
    }

    // ---- varying segment ----
    if (vend <= 0) return;
    const int s  = blockIdx.x - FILLG;
    const int A  = g_acnt[b];
    const int i0 = s * SEG;
    const int i1 = min(i0 + SEG, A);
    const int n  = max(i1 - i0, 0);
    if (s > 0 && n == 0) return;

    __shared__ int sl[SEG];
    __shared__ int st[SEG];
    __shared__ int s_end;
    if (tid < n) {
        sl[tid] = g_alist[b * VV + i0 + tid];
        st[tid] = g_atime[b * VV + i0 + tid];
    }
    if (tid == 0) s_end = (i1 < A) ? g_atime[b * VV + i1] : vend;
    __syncthreads();

    const int ts = (s == 0) ? 0 : ((n > 0) ? st[0] : vend);
    const int ve = min(s_end, vend);
    if (ts >= ve) return;                    // no rows owned by this segment

    float4 L = ((const float4*)(g_segstate + ((size_t)b * NSEG + s) * VV))[tid];

    // Static 8-deep register prefetch over Wt columns
    float4 w[8];
#pragma unroll
    for (int k = 0; k < 8; k++)
        w[k] = (k < n) ? ((const float4*)(g_Wt + (size_t)sl[k] * VV))[tid]
                       : make_float4(0.f, 0.f, 0.f, 0.f);

    int wt = ts;
    for (int base = 0; base < n; base += 8) {
#pragma unroll
        for (int k = 0; k < 8; k++) {
            const int i = base + k;
            if (i < n) {
                const int te = min(st[i], ve);
                while (wt < te) { __stcs(&obase[(size_t)wt * (VV / 4)], L); wt++; }
                L.x += w[k].x; L.y += w[k].y; L.z += w[k].z; L.w += w[k].w;
                const int j = i + 8;
                if (j < n)
                    w[k] = ((const float4*)(g_Wt + (size_t)sl[j] * VV))[tid];
            }
        }
    }
    while (wt < ve) { __stcs(&obase[(size_t)wt * (VV / 4)], L); wt++; }
}

// ---------------------------------------------------------------------------
// Launch. Inputs (metadata order): times[B,T] f32, codes[B,T,V] f32,
// lengths[B] i32, W[V,V] f32, b[V] f32. Output: [B, T-1, V] f32.
// ---------------------------------------------------------------------------
extern "C" void kernel_launch(void* const* d_in, const int* in_sizes, int n_in,
                              void* d_out, int out_size) {
    const float* codes   = (const float*)d_in[1];
    const int*   lengths = (const int*)d_in[2];
    const float* W       = (const float*)d_in[3];
    const float* bias    = (const float*)d_in[4];
    float*       out     = (float*)d_out;

    transpose_w<<<dim3(VV / 32, VV / 32), dim3(32, 8)>>>(W);
    scan_ft<<<dim3(BB, 4), 128>>>(codes);
    sort_acts<<<BB, VV>>>();
    segsum<<<dim3(NSEG, BB), VV>>>();
    segprefix<<<BB, VV>>>(bias);
    output_k<<<dim3(FILLG + NSEG, BB), 128>>>(lengths, out);
}

// round 6
// speedup vs baseline: 3.5267x; 1.0129x over previous
#include <cuda_runtime.h>
#include <cuda_bf16.h>

// Problem shape (LogRegBaseline): B=64, T=2048, V=512
#define BB    64
#define TT    2048
#define VV    512
#define TM1   (TT - 1)           // 2047 output positions
#define NSEG  8                  // activation-index segments per batch (output view)
#define SEG   64                 // activations per segment
#define NSUB  16                 // sub-segments for segsum parallelism (32 acts each)
#define FILLG 96                 // fill slices per batch

// Scratch (device globals; no allocation allowed)
__device__ int   g_ft[BB * VV];          // first-activation time per (b,v); TT if never
__device__ int   g_tlast[BB];            // max activation time per batch (0 if none)
__device__ int   g_alist[BB * VV];       // activation v's sorted by time
__device__ int   g_atime[BB * VV];       // matching sorted times
__device__ int   g_acnt[BB];             // number of activations per batch
__device__ float g_Wt[VV * VV];          // W transposed: Wt[v*VV+u] = W[u*VV+v]
__device__ float g_seg[BB * NSUB * VV];      // per-sub-segment column sums
__device__ float g_segstate[BB * NSEG * VV]; // state at segment start
__device__ float g_S[BB * VV];           // steady-state row (bias + all activations)

// ---------------------------------------------------------------------------
// Kernel 1 (fused setup), grid 384 x 256:
//   bid <  256 : W-transpose tile (16x16 tiles of 32x32)
//   bid >= 256 : first-activation scan, (b, half) = ((bid-256)>>1, (bid-256)&1)
// ---------------------------------------------------------------------------
__global__ void setup(const float* __restrict__ W, const float* __restrict__ codes) {
    const int bid = blockIdx.x;
    const int tid = threadIdx.x;

    if (bid < 256) {
        // ---- transpose W[u,v] -> Wt[v,u] ----
        __shared__ float tile[32][33];
        const int tx = tid & 31, ty = tid >> 5;        // 32 x 8
        const int bx = bid & 15, by = bid >> 4;
        int x = bx * 32 + tx;          // v
        int y = by * 32 + ty;          // u base
#pragma unroll
        for (int j = 0; j < 32; j += 8)
            tile[ty + j][tx] = W[(size_t)(y + j) * VV + x];
        __syncthreads();
        x = by * 32 + tx;              // u
        y = bx * 32 + ty;              // v base
#pragma unroll
        for (int j = 0; j < 32; j += 8)
            g_Wt[(size_t)(y + j) * VV + x] = tile[tx][ty + j];
        return;
    }

    // ---- first-activation scan (early exit at own ft) ----
    const int idx = bid - 256;         // 0..127
    const int b   = idx >> 1;
    const int v   = ((idx & 1) << 8) + tid;
    const float* p = codes + (size_t)b * TT * VV + v;
    int myft = TT;
    for (int t0 = 0; t0 < TT; t0 += 16) {
        float x[16];
#pragma unroll
        for (int k = 0; k < 16; k++) x[k] = p[(size_t)(t0 + k) * VV];
        bool hit = false;
#pragma unroll
        for (int k = 0; k < 16; k++) {
            if (!hit && x[k] != 0.0f) { hit = true; myft = t0 + k; }
        }
        if (hit) break;
    }
    g_ft[b * VV + v] = myft;
}

// ---------------------------------------------------------------------------
// Kernel 2: per-batch counting sort of activations by time + t_last.
// Grid BB x 512. Warp-shuffle scans (2 block barriers on the scan path).
// ---------------------------------------------------------------------------
__global__ void sort_acts() {
    const int b    = blockIdx.x;
    const int tid  = threadIdx.x;
    const int warp = tid >> 5, lane = tid & 31;
    __shared__ int cnt[TT];      // 8KB buckets -> cursors
    __shared__ int wred[16];     // warp partials (max, then scan)

    const int myft = g_ft[b * VV + tid];

    // t_last: warp max -> block max
    int m = (myft < TT) ? myft : 0;
#pragma unroll
    for (int off = 16; off; off >>= 1) m = max(m, __shfl_xor_sync(0xffffffffu, m, off));
    if (lane == 0) wred[warp] = m;
    __syncthreads();
    if (tid == 0) {
        int mm = 0;
#pragma unroll
        for (int i = 0; i < 16; i++) mm = max(mm, wred[i]);
        g_tlast[b] = mm;
    }
    __syncthreads();   // wred reused below

    // zero buckets + count
#pragma unroll
    for (int k = 0; k < 4; k++) cnt[k * VV + tid] = 0;
    __syncthreads();
    if (myft < TT) atomicAdd(&cnt[myft], 1);
    __syncthreads();

    // block exclusive scan of 2048 buckets (4 per thread) via warp shuffles
    const int a0 = cnt[4 * tid], a1 = cnt[4 * tid + 1];
    const int a2 = cnt[4 * tid + 2], a3 = cnt[4 * tid + 3];
    const int mysum = a0 + a1 + a2 + a3;
    int inc = mysum;
#pragma unroll
    for (int d = 1; d < 32; d <<= 1) {
        int t = __shfl_up_sync(0xffffffffu, inc, d);
        if (lane >= d) inc += t;
    }
    if (lane == 31) wred[warp] = inc;
    __syncthreads();
    if (warp == 0 && lane < 16) {
        int v = wred[lane];
#pragma unroll
        for (int d = 1; d < 16; d <<= 1) {
            int t = __shfl_up_sync(0x0000ffffu, v, d);
            if (lane >= d) v += t;
        }
        wred[lane] = v;
    }
    __syncthreads();
    const int wbase = (warp > 0) ? wred[warp - 1] : 0;
    const int ex    = wbase + inc - mysum;      // exclusive prefix of this thread's 4
    cnt[4 * tid]     = ex;
    cnt[4 * tid + 1] = ex + a0;
    cnt[4 * tid + 2] = ex + a0 + a1;
    cnt[4 * tid + 3] = ex + a0 + a1 + a2;
    if (tid == VV - 1) g_acnt[b] = wbase + inc; // grand total
    __syncthreads();

    if (myft < TT) {
        int pos = atomicAdd(&cnt[myft], 1);
        g_alist[b * VV + pos] = tid;
        g_atime[b * VV + pos] = myft;
    }
}

// ---------------------------------------------------------------------------
// Kernel 3: per-sub-segment column sums (32 activations each).
// Grid (NSUB, BB) x 512 (thread = logit lane u). 1024 CTAs.
// ---------------------------------------------------------------------------
__global__ void segsum() {
    const int sub = blockIdx.x;        // 0..15
    const int b   = blockIdx.y;
    const int u   = threadIdx.x;
    __shared__ int sl[32];

    const int A  = g_acnt[b];
    const int i0 = sub * 32;
    const int i1 = min(i0 + 32, A);
    const int n  = max(i1 - i0, 0);

    if (u < 32 && u < n) sl[u] = g_alist[b * VV + i0 + u];
    __syncthreads();

    float acc = 0.0f;
    int i = 0;
    for (; i + 8 <= n; i += 8) {
        float w0 = g_Wt[sl[i + 0] * VV + u];
        float w1 = g_Wt[sl[i + 1] * VV + u];
        float w2 = g_Wt[sl[i + 2] * VV + u];
        float w3 = g_Wt[sl[i + 3] * VV + u];
        float w4 = g_Wt[sl[i + 4] * VV + u];
        float w5 = g_Wt[sl[i + 5] * VV + u];
        float w6 = g_Wt[sl[i + 6] * VV + u];
        float w7 = g_Wt[sl[i + 7] * VV + u];
        acc += ((w0 + w1) + (w2 + w3)) + ((w4 + w5) + (w6 + w7));
    }
    for (; i < n; i++) acc += g_Wt[sl[i] * VV + u];

    g_seg[((size_t)b * NSUB + sub) * VV + u] = acc;
}

// ---------------------------------------------------------------------------
// Kernel 4: prefix over 16 sub-sums -> 8 segment-start states + steady row S.
// Grid BB x 512.
// ---------------------------------------------------------------------------
__global__ void segprefix(const float* __restrict__ bias) {
    const int b = blockIdx.x;
    const int u = threadIdx.x;
    float sg[NSUB];
#pragma unroll
    for (int s = 0; s < NSUB; s++) sg[s] = g_seg[((size_t)b * NSUB + s) * VV + u];
    float run = bias[u];
#pragma unroll
    for (int s = 0; s < NSEG; s++) {
        g_segstate[((size_t)b * NSEG + s) * VV + u] = run;
        run += sg[2 * s] + sg[2 * s + 1];
    }
    g_S[b * VV + u] = run;
}

// ---------------------------------------------------------------------------
// Kernel 5 (fused output), grid (FILLG + NSEG, BB) x 128:
//   blockIdx.x <  FILLG : constant-region fill slice, rows [vend, TM1)
//   blockIdx.x >= FILLG : varying segment s, rows between sorted act times.
// vend = min(t_last, limit); rows t >= limit are zeros.
// ---------------------------------------------------------------------------
__global__ void output_k(const int* __restrict__ lengths, float* __restrict__ out) {
    const int b     = blockIdx.y;
    const int tid   = threadIdx.x;          // float4 lane
    const int limit = lengths[b] - 1;
    const int vend  = min(g_tlast[b], limit);

    float4* obase = (float4*)out + (size_t)b * TM1 * (VV / 4) + tid;

    if (blockIdx.x < FILLG) {
        // ---- fill slice ----
        const int total = TM1 - vend;
        if (total <= 0) return;
        const int per = (total + FILLG - 1) / FILLG;
        const int r0  = vend + blockIdx.x * per;
        const int r1  = min(r0 + per, TM1);
        if (r0 >= r1) return;

        const float4 S = ((const float4*)(g_S + (size_t)b * VV))[tid];
        const float4 Z = make_float4(0.f, 0.f, 0.f, 0.f);
#pragma unroll 8
        for (int t = r0; t < r1; t++) {
            float4 val = (t < limit) ? S : Z;
            __stcs(&obase[(size_t)t * (VV / 4)], val);
        }
        return;
    }

    // ---- varying segment ----
    if (vend <= 0) return;
    const int s  = blockIdx.x - FILLG;
    const int A  = g_acnt[b];
    const int i0 = s * SEG;
    const int i1 = min(i0 + SEG, A);
    const int n  = max(i1 - i0, 0);
    if (s > 0 && n == 0) return;

    __shared__ int sl[SEG];
    __shared__ int st[SEG];
    __shared__ int s_end;
    if (tid < n) {
        sl[tid] = g_alist[b * VV + i0 + tid];
        st[tid] = g_atime[b * VV + i0 + tid];
    }
    if (tid == 0) s_end = (i1 < A) ? g_atime[b * VV + i1] : vend;
    __syncthreads();

    const int ts = (s == 0) ? 0 : ((n > 0) ? st[0] : vend);
    const int ve = min(s_end, vend);
    if (ts >= ve) return;

    float4 L = ((const float4*)(g_segstate + ((size_t)b * NSEG + s) * VV))[tid];

    // Static 8-deep register prefetch over Wt columns
    float4 w[8];
#pragma unroll
    for (int k = 0; k < 8; k++)
        w[k] = (k < n) ? ((const float4*)(g_Wt + (size_t)sl[k] * VV))[tid]
                       : make_float4(0.f, 0.f, 0.f, 0.f);

    int wt = ts;
    for (int base = 0; base < n; base += 8) {
#pragma unroll
        for (int k = 0; k < 8; k++) {
            const int i = base + k;
            if (i < n) {
                const int te = min(st[i], ve);
                while (wt < te) { __stcs(&obase[(size_t)wt * (VV / 4)], L); wt++; }
                L.x += w[k].x; L.y += w[k].y; L.z += w[k].z; L.w += w[k].w;
                const int j = i + 8;
                if (j < n)
                    w[k] = ((const float4*)(g_Wt + (size_t)sl[j] * VV))[tid];
            }
        }
    }
    while (wt < ve) { __stcs(&obase[(size_t)wt * (VV / 4)], L); wt++; }
}

// ---------------------------------------------------------------------------
// Launch. Inputs (metadata order): times[B,T] f32, codes[B,T,V] f32,
// lengths[B] i32, W[V,V] f32, b[V] f32. Output: [B, T-1, V] f32.
// ---------------------------------------------------------------------------
extern "C" void kernel_launch(void* const* d_in, const int* in_sizes, int n_in,
                              void* d_out, int out_size) {
    const float* codes   = (const float*)d_in[1];
    const int*   lengths = (const int*)d_in[2];
    const float* W       = (const float*)d_in[3];
    const float* bias    = (const float*)d_in[4];
    float*       out     = (float*)d_out;

    setup<<<384, 256>>>(W, codes);
    sort_acts<<<BB, VV>>>();
    segsum<<<dim3(NSUB, BB), VV>>>();
    segprefix<<<BB, VV>>>(bias);
    output_k<<<dim3(FILLG + NSEG, BB), 128>>>(lengths, out);
}

// round 7
// speedup vs baseline: 3.6216x; 1.0269x over previous
#include <cuda_runtime.h>
#include <cuda_bf16.h>

// Problem shape (LogRegBaseline): B=64, T=2048, V=512
#define BB    64
#define TT    2048
#define VV    512
#define TM1   (TT - 1)           // 2047 output positions
#define NSEG  8                  // activation-index segments per batch (output view)
#define SEG   64                 // activations per segment
#define NSUB  16                 // sub-segments for segsum (32 acts each)
#define FILLG 64                 // S-fill slices per batch
#define ZFG   32                 // zero-fill slices per batch (in setup)

// Scratch (device globals; no allocation allowed)
__device__ int   g_ft[BB * VV];          // first-activation time per (b,v); TT if never
__device__ int   g_tlast[BB];            // max activation time per batch (0 if none)
__device__ int   g_alist[BB * VV];       // activation v's sorted by time
__device__ int   g_atime[BB * VV];       // matching sorted times
__device__ int   g_acnt[BB];             // number of activations per batch
__device__ float g_Wt[VV * VV];          // W transposed: Wt[v*VV+u] = W[u*VV+v]
__device__ float g_seg[BB * NSUB * VV];  // per-sub-segment column sums

// ---------------------------------------------------------------------------
// Kernel 1 (fused setup), grid (384 + ZFG*BB) x 256:
//   bid <  256            : W-transpose tile
//   256 <= bid < 384      : first-activation scan
//   bid >= 384            : zero-fill rows [limit, TM1)  (needs only lengths)
// ---------------------------------------------------------------------------
__global__ void setup(const float* __restrict__ W, const float* __restrict__ codes,
                      const int* __restrict__ lengths, float* __restrict__ out) {
    const int bid = blockIdx.x;
    const int tid = threadIdx.x;

    if (bid < 256) {
        // ---- transpose W[u,v] -> Wt[v,u] ----
        __shared__ float tile[32][33];
        const int tx = tid & 31, ty = tid >> 5;        // 32 x 8
        const int bx = bid & 15, by = bid >> 4;
        int x = bx * 32 + tx;
        int y = by * 32 + ty;
#pragma unroll
        for (int j = 0; j < 32; j += 8)
            tile[ty + j][tx] = W[(size_t)(y + j) * VV + x];
        __syncthreads();
        x = by * 32 + tx;
        y = bx * 32 + ty;
#pragma unroll
        for (int j = 0; j < 32; j += 8)
            g_Wt[(size_t)(y + j) * VV + x] = tile[tx][ty + j];
        return;
    }

    if (bid < 384) {
        // ---- first-activation scan (early exit at own ft) ----
        const int idx = bid - 256;         // 0..127
        const int b   = idx >> 1;
        const int v   = ((idx & 1) << 8) + tid;
        const float* p = codes + (size_t)b * TT * VV + v;
        int myft = TT;
        for (int t0 = 0; t0 < TT; t0 += 16) {
            float x[16];
#pragma unroll
            for (int k = 0; k < 16; k++) x[k] = p[(size_t)(t0 + k) * VV];
            bool hit = false;
#pragma unroll
            for (int k = 0; k < 16; k++) {
                if (!hit && x[k] != 0.0f) { hit = true; myft = t0 + k; }
            }
            if (hit) break;
        }
        g_ft[b * VV + v] = myft;
        return;
    }

    // ---- zero-fill rows [limit, TM1) ----
    const int z     = bid - 384;
    const int b     = z >> 5;              // ZFG = 32
    const int slice = z & (ZFG - 1);
    const int limit = lengths[b] - 1;
    const int total = TM1 - limit;
    if (total <= 0) return;
    const int per = (total + ZFG - 1) / ZFG;
    const int r0  = limit + slice * per;
    const int r1  = min(r0 + per, TM1);
    if (r0 >= r1) return;

    const int lane = tid & 127;            // float4 lane
    const int sub  = tid >> 7;             // 0/1 row phase
    float4* obase = (float4*)out + (size_t)b * TM1 * (VV / 4) + lane;
    const float4 Z = make_float4(0.f, 0.f, 0.f, 0.f);
    for (int t = r0 + sub; t < r1; t += 2)
        __stcs(&obase[(size_t)t * (VV / 4)], Z);
}

// ---------------------------------------------------------------------------
// Kernel 2: per-batch counting sort of activations by time + t_last.
// Grid BB x 512. Warp-shuffle scans.
// ---------------------------------------------------------------------------
__global__ void sort_acts() {
    const int b    = blockIdx.x;
    const int tid  = threadIdx.x;
    const int warp = tid >> 5, lane = tid & 31;
    __shared__ int cnt[TT];      // buckets -> cursors
    __shared__ int wred[16];

    const int myft = g_ft[b * VV + tid];

    // t_last
    int m = (myft < TT) ? myft : 0;
#pragma unroll
    for (int off = 16; off; off >>= 1) m = max(m, __shfl_xor_sync(0xffffffffu, m, off));
    if (lane == 0) wred[warp] = m;
    __syncthreads();
    if (tid == 0) {
        int mm = 0;
#pragma unroll
        for (int i = 0; i < 16; i++) mm = max(mm, wred[i]);
        g_tlast[b] = mm;
    }
    __syncthreads();

#pragma unroll
    for (int k = 0; k < 4; k++) cnt[k * VV + tid] = 0;
    __syncthreads();
    if (myft < TT) atomicAdd(&cnt[myft], 1);
    __syncthreads();

    const int a0 = cnt[4 * tid], a1 = cnt[4 * tid + 1];
    const int a2 = cnt[4 * tid + 2], a3 = cnt[4 * tid + 3];
    const int mysum = a0 + a1 + a2 + a3;
    int inc = mysum;
#pragma unroll
    for (int d = 1; d < 32; d <<= 1) {
        int t = __shfl_up_sync(0xffffffffu, inc, d);
        if (lane >= d) inc += t;
    }
    if (lane == 31) wred[warp] = inc;
    __syncthreads();
    if (warp == 0 && lane < 16) {
        int v = wred[lane];
#pragma unroll
        for (int d = 1; d < 16; d <<= 1) {
            int t = __shfl_up_sync(0x0000ffffu, v, d);
            if (lane >= d) v += t;
        }
        wred[lane] = v;
    }
    __syncthreads();
    const int wbase = (warp > 0) ? wred[warp - 1] : 0;
    const int ex    = wbase + inc - mysum;
    cnt[4 * tid]     = ex;
    cnt[4 * tid + 1] = ex + a0;
    cnt[4 * tid + 2] = ex + a0 + a1;
    cnt[4 * tid + 3] = ex + a0 + a1 + a2;
    if (tid == VV - 1) g_acnt[b] = wbase + inc;
    __syncthreads();

    if (myft < TT) {
        int pos = atomicAdd(&cnt[myft], 1);
        g_alist[b * VV + pos] = tid;
        g_atime[b * VV + pos] = myft;
    }
}

// ---------------------------------------------------------------------------
// Kernel 3: per-sub-segment column sums (32 sorted activations each).
// Grid (NSUB, BB) x 512 (thread = logit lane u).
// ---------------------------------------------------------------------------
__global__ void segsum() {
    const int sub = blockIdx.x;
    const int b   = blockIdx.y;
    const int u   = threadIdx.x;
    __shared__ int sl[32];

    const int A  = g_acnt[b];
    const int i0 = sub * 32;
    const int i1 = min(i0 + 32, A);
    const int n  = max(i1 - i0, 0);

    if (u < 32 && u < n) sl[u] = g_alist[b * VV + i0 + u];
    __syncthreads();

    float acc = 0.0f;
    int i = 0;
    for (; i + 8 <= n; i += 8) {
        float w0 = g_Wt[sl[i + 0] * VV + u];
        float w1 = g_Wt[sl[i + 1] * VV + u];
        float w2 = g_Wt[sl[i + 2] * VV + u];
        float w3 = g_Wt[sl[i + 3] * VV + u];
        float w4 = g_Wt[sl[i + 4] * VV + u];
        float w5 = g_Wt[sl[i + 5] * VV + u];
        float w6 = g_Wt[sl[i + 6] * VV + u];
        float w7 = g_Wt[sl[i + 7] * VV + u];
        acc += ((w0 + w1) + (w2 + w3)) + ((w4 + w5) + (w6 + w7));
    }
    for (; i < n; i++) acc += g_Wt[sl[i] * VV + u];

    g_seg[((size_t)b * NSUB + sub) * VV + u] = acc;
}

// ---------------------------------------------------------------------------
// Kernel 4 (output), grid (FILLG + NSEG, BB) x 128:
//   blockIdx.x <  FILLG : S-fill slice, rows [vend, limit)   (zeros done in setup)
//   blockIdx.x >= FILLG : varying segment s, rows between sorted act times.
// Starting states computed locally from bias + g_seg prefix (no segprefix kernel).
// ---------------------------------------------------------------------------
__global__ void output_k(const int* __restrict__ lengths, const float* __restrict__ bias,
                         float* __restrict__ out) {
    const int b     = blockIdx.y;
    const int tid   = threadIdx.x;          // float4 lane
    const int limit = lengths[b] - 1;
    const int vend  = min(g_tlast[b], limit);

    float4* obase = (float4*)out + (size_t)b * TM1 * (VV / 4) + tid;
    const float4* seg4  = (const float4*)(g_seg + (size_t)b * NSUB * VV);
    const float4* bias4 = (const float4*)bias;

    if (blockIdx.x < FILLG) {
        // ---- S-fill slice over [vend, limit) ----
        const int total = limit - vend;
        if (total <= 0) return;
        const int per = (total + FILLG - 1) / FILLG;
        const int r0  = vend + blockIdx.x * per;
        const int r1  = min(r0 + per, limit);
        if (r0 >= r1) return;

        // S = bias + sum of all 16 sub-sums
        float4 S = bias4[tid];
#pragma unroll
        for (int s = 0; s < NSUB; s++) {
            float4 g = seg4[s * (VV / 4) + tid];
            S.x += g.x; S.y += g.y; S.z += g.z; S.w += g.w;
        }
#pragma unroll 8
        for (int t = r0; t < r1; t++)
            __stcs(&obase[(size_t)t * (VV / 4)], S);
        return;
    }

    // ---- varying segment ----
    if (vend <= 0) return;
    const int s  = blockIdx.x - FILLG;
    const int A  = g_acnt[b];
    const int i0 = s * SEG;
    const int i1 = min(i0 + SEG, A);
    const int n  = max(i1 - i0, 0);
    if (s > 0 && n == 0) return;

    __shared__ int sl[SEG];
    __shared__ int st[SEG];
    __shared__ int s_end;
    if (tid < n) {
        sl[tid] = g_alist[b * VV + i0 + tid];
        st[tid] = g_atime[b * VV + i0 + tid];
    }
    if (tid == 0) s_end = (i1 < A) ? g_atime[b * VV + i1] : vend;
    __syncthreads();

    const int ts = (s == 0) ? 0 : ((n > 0) ? st[0] : vend);
    const int ve = min(s_end, vend);
    if (ts >= ve) return;

    // Starting state = bias + sub-sums [0, 2s)
    float4 L = bias4[tid];
    for (int q = 0; q < 2 * s; q++) {
        float4 g = seg4[q * (VV / 4) + tid];
        L.x += g.x; L.y += g.y; L.z += g.z; L.w += g.w;
    }

    // Static 8-deep register prefetch over Wt columns
    float4 w[8];
#pragma unroll
    for (int k = 0; k < 8; k++)
        w[k] = (k < n) ? ((const float4*)(g_Wt + (size_t)sl[k] * VV))[tid]
                       : make_float4(0.f, 0.f, 0.f, 0.f);

    int wt = ts;
    for (int base = 0; base < n; base += 8) {
#pragma unroll
        for (int k = 0; k < 8; k++) {
            const int i = base + k;
            if (i < n) {
                const int te = min(st[i], ve);
                while (wt < te) { __stcs(&obase[(size_t)wt * (VV / 4)], L); wt++; }
                L.x += w[k].x; L.y += w[k].y; L.z += w[k].z; L.w += w[k].w;
                const int j = i + 8;
                if (j < n)
                    w[k] = ((const float4*)(g_Wt + (size_t)sl[j] * VV))[tid];
            }
        }
    }
    while (wt < ve) { __stcs(&obase[(size_t)wt * (VV / 4)], L); wt++; }
}

// ---------------------------------------------------------------------------
// Launch. Inputs (metadata order): times[B,T] f32, codes[B,T,V] f32,
// lengths[B] i32, W[V,V] f32, b[V] f32. Output: [B, T-1, V] f32.
// ---------------------------------------------------------------------------
extern "C" void kernel_launch(void* const* d_in, const int* in_sizes, int n_in,
                              void* d_out, int out_size) {
    const float* codes   = (const float*)d_in[1];
    const int*   lengths = (const int*)d_in[2];
    const float* W       = (const float*)d_in[3];
    const float* bias    = (const float*)d_in[4];
    float*       out     = (float*)d_out;

    setup<<<384 + ZFG * BB, 256>>>(W, codes, lengths, out);
    sort_acts<<<BB, VV>>>();
    segsum<<<dim3(NSUB, BB), VV>>>();
    output_k<<<dim3(FILLG + NSEG, BB), 128>>>(lengths, bias, out);
}